// round 7
// baseline (speedup 1.0000x reference)
#include <cuda_runtime.h>
#include <cuda_fp16.h>
#include <cstdint>

// ===========================================================================
// Cross_26998164423018  (B=8, N=2048, C=576, H=1)
// Round 7: fp16 m16n8k16 + ldmatrix.x4 fragment loads (48 LDS -> 12 ldmatrix
// per K-32 iteration), 4-stage cp.async pipeline.
// ===========================================================================

#define CDIM   576
#define NTOK   2048
#define BATCH  8
#define ROWS   (BATCH * NTOK)          // 16384
#define ATT_SCALE 0.0416666679f        // 1/24

#define STAGES      4
#define ROW_HALVES  40                 // 32 data + 8 pad (80B row)
#define ROW_BYTES   80
#define TILE_BYTES  (128 * ROW_BYTES)               // 10240
#define STAGE_BYTES (2 * TILE_BYTES)                // A+B = 20480
#define EH          136                // half epilogue stride
#define EF          132                // float epilogue stride
#define SMEM_SZ     (STAGES * STAGE_BYTES)          // 81920

// ------------------------- scratch (static device mem) ---------------------
__device__ float  g_xnf[(size_t)ROWS * CDIM];      // fp32 xn (residual)
__device__ __half g_xnh[(size_t)ROWS * CDIM];
__device__ __half g_ynh[(size_t)ROWS * CDIM];
__device__ __half g_wq [(size_t)CDIM * CDIM];
__device__ __half g_wk [(size_t)CDIM * CDIM];
__device__ __half g_wv [(size_t)CDIM * CDIM];
__device__ __half g_wp [(size_t)CDIM * CDIM];
__device__ __half g_q  [(size_t)ROWS * CDIM];
__device__ __half g_k  [(size_t)ROWS * CDIM];
__device__ __half g_vt [(size_t)BATCH * CDIM * NTOK];   // [b][n][t]
__device__ __half g_o  [(size_t)ROWS * CDIM];
__device__ __half g_attn[(size_t)BATCH * NTOK * NTOK];  // 67 MB
__device__ float  g_p  [(size_t)ROWS * CDIM];

// ------------------------------- helpers -----------------------------------
__device__ __forceinline__ uint32_t smem_u32(const void* p) {
    uint32_t a;
    asm("{ .reg .u64 t; cvta.to.shared.u64 t, %1; cvt.u32.u64 %0, t; }"
        : "=r"(a) : "l"(p));
    return a;
}
__device__ __forceinline__ void cpa16(uint32_t dst, const void* src, uint32_t sz) {
    asm volatile("cp.async.cg.shared.global [%0], [%1], 16, %2;"
                 :: "r"(dst), "l"(src), "r"(sz) : "memory");
}
__device__ __forceinline__ void cpa_commit() {
    asm volatile("cp.async.commit_group;" ::: "memory");
}
template<int Np> __device__ __forceinline__ void cpa_wait() {
    asm volatile("cp.async.wait_group %0;" :: "n"(Np) : "memory");
}
__device__ __forceinline__ void mma_f16(float* c, const uint32_t* a, const uint32_t* b) {
    asm volatile(
        "mma.sync.aligned.m16n8k16.row.col.f32.f16.f16.f32 "
        "{%0,%1,%2,%3}, {%4,%5,%6,%7}, {%8,%9}, {%0,%1,%2,%3};"
        : "+f"(c[0]), "+f"(c[1]), "+f"(c[2]), "+f"(c[3])
        : "r"(a[0]), "r"(a[1]), "r"(a[2]), "r"(a[3]), "r"(b[0]), "r"(b[1]));
}
__device__ __forceinline__ void ldsm_x4(uint32_t* r, uint32_t addr) {
    asm volatile("ldmatrix.sync.aligned.m8n8.x4.shared.b16 {%0,%1,%2,%3}, [%4];"
        : "=r"(r[0]), "=r"(r[1]), "=r"(r[2]), "=r"(r[3]) : "r"(addr));
}

// ===========================================================================
// fp16 mma.sync GEMM: C[M,N] = A[M,K] @ B[N,K]^T  (both K-major, half)
// grid: (x = N-tiles, y = M-tiles, z = batch), block = 256 (8 warps, 2x4)
// EPI: 1 = half store, 2 = sigmoid(x/24) half store,
//      3 = fp32 store + bias[n] + resid[m,n], 4 = transposed half store (Vt)
// ===========================================================================
template<int EPI>
__global__ __launch_bounds__(256) void mma_gemm(
    const __half* __restrict__ A, const __half* __restrict__ B,
    void* __restrict__ Cv, int M, int N, int K,
    long sAz, long sBz, long sCz, int ldC,
    const float* __restrict__ bias, const float* __restrict__ resid)
{
    extern __shared__ char smem[];
    const uint32_t sb = smem_u32(smem);
    const int tid  = threadIdx.x;
    const int lane = tid & 31;
    const int wid  = tid >> 5;
    const int m0 = blockIdx.y * 128;
    const int n0 = blockIdx.x * 128;
    const int z  = blockIdx.z;
    const int KT = K >> 5;

    // ---- gmem load mapping: thread owns row tid>>1, 32B half (tid&1) ----
    const int lrow  = tid >> 1;
    const int lhalf = tid & 1;
    const __half* aPtr = A + (size_t)z * sAz + (size_t)(m0 + lrow) * K + lhalf * 16;
    const int gn = n0 + lrow;
    const uint32_t bsz = (gn < N) ? 16u : 0u;
    const __half* bPtr = B + (size_t)z * sBz + (size_t)(gn < N ? gn : 0) * K + lhalf * 16;
    const uint32_t dA = sb + (uint32_t)lrow * ROW_BYTES + (uint32_t)lhalf * 32;
    const uint32_t dB = dA + TILE_BYTES;

    auto load_stage = [&](int s, int kt) {
        const uint32_t so = (uint32_t)s * STAGE_BYTES;
        const int k0 = kt * 32;
        cpa16(dA + so,      aPtr + k0,     16u);
        cpa16(dA + so + 16, aPtr + k0 + 8, 16u);
        cpa16(dB + so,      bPtr + k0,     bsz);
        cpa16(dB + so + 16, bPtr + k0 + 8, bsz);
    };

    // ---- accumulators & frag coords ----
    float acc[4][4][4];
    #pragma unroll
    for (int mt = 0; mt < 4; mt++)
        #pragma unroll
        for (int nt = 0; nt < 4; nt++)
            #pragma unroll
            for (int i = 0; i < 4; i++) acc[mt][nt][i] = 0.f;

    const int warp_m = wid & 1;
    const int warp_n = wid >> 1;
    const int gid = lane >> 2;           // groupID 0..7
    const int tig = lane & 3;            // thread-in-group

    // ---- ldmatrix per-lane base addresses (stage 0) ----
    // A x4 tile (16 rows x 16 k-halves): lanes 0-15 -> rows, lanes 16-31 -> +16B k
    const uint32_t aLdBase = sb
        + (uint32_t)(warp_m * 64 + (lane & 15)) * ROW_BYTES
        + (uint32_t)(lane >> 4) * 16;
    // B x4: quads 0/1 = n rows +0..7 (k +0 / +16B), quads 2/3 = n rows +8..15
    const uint32_t bLdBase = sb + TILE_BYTES
        + (uint32_t)(warp_n * 32 + (lane & 7) + ((lane >> 4) & 1) * 8) * ROW_BYTES
        + (uint32_t)((lane >> 3) & 1) * 16;

    // ---- pipeline prologue: stages 0..2 ----
    load_stage(0, 0); cpa_commit();
    load_stage(1, 1); cpa_commit();
    load_stage(2, 2); cpa_commit();

    for (int kt = 0; kt < KT; kt++) {
        cpa_wait<2>();
        __syncthreads();
        if (kt + 3 < KT) load_stage((kt + 3) & (STAGES - 1), kt + 3);
        cpa_commit();

        const uint32_t so = (uint32_t)(kt & (STAGES - 1)) * STAGE_BYTES;

        #pragma unroll
        for (int kk = 0; kk < 2; kk++) {
            const uint32_t ko = so + (uint32_t)kk * 32;
            uint32_t af[4][4];
            #pragma unroll
            for (int mt = 0; mt < 4; mt++)
                ldsm_x4(af[mt], aLdBase + ko + (uint32_t)mt * (16 * ROW_BYTES));
            uint32_t bf[8];
            #pragma unroll
            for (int p = 0; p < 2; p++)
                ldsm_x4(bf + p * 4, bLdBase + ko + (uint32_t)p * (16 * ROW_BYTES));
            #pragma unroll
            for (int mt = 0; mt < 4; mt++)
                #pragma unroll
                for (int nt = 0; nt < 4; nt++)
                    mma_f16(acc[mt][nt], af[mt], bf + ((nt >> 1) * 4 + (nt & 1) * 2));
        }
    }

    // drain pending prefetches before reusing smem
    cpa_wait<0>();
    __syncthreads();

    // -------------------------------- epilogue --------------------------------
    if (EPI == 3) {
        float* eb = (float*)smem;   // [128][EF]
        #pragma unroll
        for (int mt = 0; mt < 4; mt++)
            #pragma unroll
            for (int i = 0; i < 4; i++) {
                const int r = warp_m * 64 + mt * 16 + gid + ((i >= 2) ? 8 : 0);
                #pragma unroll
                for (int nt = 0; nt < 4; nt++) {
                    const int c = warp_n * 32 + nt * 8 + tig * 2 + (i & 1);
                    eb[r * EF + c] = acc[mt][nt][i];
                }
            }
        __syncthreads();
        float* C = (float*)Cv;
        #pragma unroll
        for (int it = 0; it < 16; it++) {
            const int lin = it * 256 + tid;
            const int c4 = lin & 31, r = lin >> 5;
            const int n = n0 + c4 * 4;
            if (n < N) {
                float4 v4 = *(const float4*)(eb + r * EF + c4 * 4);
                const float4 bb = *(const float4*)(bias + n);
                const float4 rr = *(const float4*)(resid + (size_t)(m0 + r) * ldC + n);
                v4.x += bb.x + rr.x; v4.y += bb.y + rr.y;
                v4.z += bb.z + rr.z; v4.w += bb.w + rr.w;
                *(float4*)(C + (size_t)(m0 + r) * ldC + n) = v4;
            }
        }
        return;
    }

    __half* ebh = (__half*)smem;
    if (EPI == 4) {
        // transposed staging: ebh[n_local][t_local]
        #pragma unroll
        for (int mt = 0; mt < 4; mt++)
            #pragma unroll
            for (int i = 0; i < 4; i++) {
                const int r = warp_m * 64 + mt * 16 + gid + ((i >= 2) ? 8 : 0);
                #pragma unroll
                for (int nt = 0; nt < 4; nt++) {
                    const int c = warp_n * 32 + nt * 8 + tig * 2 + (i & 1);
                    ebh[c * EH + r] = __float2half_rn(acc[mt][nt][i]);
                }
            }
        __syncthreads();
        const int b = m0 >> 11, t0 = m0 & 2047;
        __half* vb = (__half*)Cv + (size_t)b * CDIM * NTOK + t0;
        #pragma unroll
        for (int it = 0; it < 8; it++) {
            const int lin = it * 256 + tid;
            const int t8 = (lin & 15) * 8, n = lin >> 4;
            if (n0 + n < N)
                *(uint4*)(vb + (size_t)(n0 + n) * NTOK + t8) =
                    *(const uint4*)(ebh + n * EH + t8);
        }
        return;
    }

    // EPI 1 / 2: half store, optionally sigmoid
    #pragma unroll
    for (int mt = 0; mt < 4; mt++)
        #pragma unroll
        for (int ih = 0; ih < 2; ih++) {       // c0c1 then c2c3 (row +8)
            const int r = warp_m * 64 + mt * 16 + gid + ih * 8;
            #pragma unroll
            for (int nt = 0; nt < 4; nt++) {
                const int c = warp_n * 32 + nt * 8 + tig * 2;
                float v0 = acc[mt][nt][ih * 2], v1 = acc[mt][nt][ih * 2 + 1];
                if (EPI == 2) {
                    v0 = 1.0f / (1.0f + __expf(-v0 * ATT_SCALE));
                    v1 = 1.0f / (1.0f + __expf(-v1 * ATT_SCALE));
                }
                *(__half2*)(ebh + r * EH + c) = __floats2half2_rn(v0, v1);
            }
        }
    __syncthreads();
    {
        __half* C = (__half*)Cv + (size_t)z * sCz;
        #pragma unroll
        for (int it = 0; it < 8; it++) {
            const int lin = it * 256 + tid;
            const int c8 = lin & 15, r = lin >> 4;
            const int n = n0 + c8 * 8;
            if (n < N)
                *(uint4*)(C + (size_t)(m0 + r) * ldC + n) =
                    *(const uint4*)(ebh + r * EH + c8 * 8);
        }
    }
}

// ===========================================================================
// LayerNorm over 576; writes fp32 and/or half output.
// ===========================================================================
__global__ __launch_bounds__(256) void ln_kernel(
    const float* __restrict__ x, const float* __restrict__ g,
    const float* __restrict__ b, float* __restrict__ out_f,
    __half* __restrict__ out_h)
{
    const long row = blockIdx.x;
    const float* xr = x + row * (long)CDIM;
    const int t = threadIdx.x;

    float v0 = xr[t];
    float v1 = xr[t + 256];
    float v2 = (t < 64) ? xr[t + 512] : 0.f;

    float s  = v0 + v1 + v2;
    float ss = v0 * v0 + v1 * v1 + v2 * v2;
    #pragma unroll
    for (int o = 16; o > 0; o >>= 1) {
        s  += __shfl_xor_sync(0xFFFFFFFFu, s,  o);
        ss += __shfl_xor_sync(0xFFFFFFFFu, ss, o);
    }
    __shared__ float sh_s[8], sh_ss[8];
    const int w = t >> 5, l = t & 31;
    if (l == 0) { sh_s[w] = s; sh_ss[w] = ss; }
    __syncthreads();
    float stot = 0.f, sstot = 0.f;
    #pragma unroll
    for (int i = 0; i < 8; i++) { stot += sh_s[i]; sstot += sh_ss[i]; }

    const float inv_n = 1.0f / (float)CDIM;
    const float mean = stot * inv_n;
    const float var  = sstot * inv_n - mean * mean;
    const float rstd = rsqrtf(var + 1e-5f);

    float o0 = (v0 - mean) * rstd * g[t]       + b[t];
    float o1 = (v1 - mean) * rstd * g[t + 256] + b[t + 256];
    float o2 = (t < 64) ? ((v2 - mean) * rstd * g[t + 512] + b[t + 512]) : 0.f;

    if (out_f) {
        out_f[row * (long)CDIM + t]       = o0;
        out_f[row * (long)CDIM + t + 256] = o1;
        if (t < 64) out_f[row * (long)CDIM + t + 512] = o2;
    }
    if (out_h) {
        out_h[row * (long)CDIM + t]       = __float2half_rn(o0);
        out_h[row * (long)CDIM + t + 256] = __float2half_rn(o1);
        if (t < 64) out_h[row * (long)CDIM + t + 512] = __float2half_rn(o2);
    }
}

__global__ void h_convert(const float* __restrict__ in, __half* __restrict__ out, int n) {
    int i = blockIdx.x * blockDim.x + threadIdx.x;
    if (i < n) out[i] = __float2half_rn(in[i]);
}

// ===========================================================================
extern "C" void kernel_launch(void* const* d_in, const int* in_sizes, int n_in,
                              void* d_out, int out_size)
{
    const float* x  = (const float*)d_in[0];
    const float* y  = (const float*)d_in[1];
    const float* Wq = (const float*)d_in[2];
    const float* Wk = (const float*)d_in[3];
    const float* Wv = (const float*)d_in[4];
    const float* Wp = (const float*)d_in[5];
    const float* bp = (const float*)d_in[6];
    const float* gx = (const float*)d_in[7];
    const float* bx = (const float*)d_in[8];
    const float* gy = (const float*)d_in[9];
    const float* by = (const float*)d_in[10];
    const float* gz = (const float*)d_in[11];
    const float* bz = (const float*)d_in[12];
    float* out = (float*)d_out;

    float *xnf, *p;
    __half *xnh, *ynh, *wq, *wk, *wv, *wp, *q, *k, *vt, *o, *attn;
    cudaGetSymbolAddress((void**)&xnf, g_xnf);
    cudaGetSymbolAddress((void**)&xnh, g_xnh);
    cudaGetSymbolAddress((void**)&ynh, g_ynh);
    cudaGetSymbolAddress((void**)&wq,  g_wq);
    cudaGetSymbolAddress((void**)&wk,  g_wk);
    cudaGetSymbolAddress((void**)&wv,  g_wv);
    cudaGetSymbolAddress((void**)&wp,  g_wp);
    cudaGetSymbolAddress((void**)&q,   g_q);
    cudaGetSymbolAddress((void**)&k,   g_k);
    cudaGetSymbolAddress((void**)&vt,  g_vt);
    cudaGetSymbolAddress((void**)&o,   g_o);
    cudaGetSymbolAddress((void**)&attn,g_attn);
    cudaGetSymbolAddress((void**)&p,   g_p);

    cudaFuncSetAttribute(mma_gemm<1>, cudaFuncAttributeMaxDynamicSharedMemorySize, SMEM_SZ);
    cudaFuncSetAttribute(mma_gemm<2>, cudaFuncAttributeMaxDynamicSharedMemorySize, SMEM_SZ);
    cudaFuncSetAttribute(mma_gemm<3>, cudaFuncAttributeMaxDynamicSharedMemorySize, SMEM_SZ);
    cudaFuncSetAttribute(mma_gemm<4>, cudaFuncAttributeMaxDynamicSharedMemorySize, SMEM_SZ);

    // 1. LayerNorms (fp32 residual copy + half operand copy)
    ln_kernel<<<ROWS, 256>>>(x, gx, bx, xnf, xnh);
    ln_kernel<<<ROWS, 256>>>(y, gy, by, nullptr, ynh);

    // 2. weights -> half
    {
        const int n = CDIM * CDIM, nb = (n + 255) / 256;
        h_convert<<<nb, 256>>>(Wq, wq, n);
        h_convert<<<nb, 256>>>(Wk, wk, n);
        h_convert<<<nb, 256>>>(Wv, wv, n);
        h_convert<<<nb, 256>>>(Wp, wp, n);
    }

    // 3. projections: q = yn@Wq^T, k = xn@Wk^T, Vt = (xn@Wv^T)^T per batch
    {
        dim3 grid(5, 128, 1);
        mma_gemm<1><<<grid, 256, SMEM_SZ>>>(ynh, wq, q,  ROWS, CDIM, CDIM, 0, 0, 0, CDIM, nullptr, nullptr);
        mma_gemm<1><<<grid, 256, SMEM_SZ>>>(xnh, wk, k,  ROWS, CDIM, CDIM, 0, 0, 0, CDIM, nullptr, nullptr);
        mma_gemm<4><<<grid, 256, SMEM_SZ>>>(xnh, wv, vt, ROWS, CDIM, CDIM, 0, 0, 0, CDIM, nullptr, nullptr);
    }

    // 4. attn = sigmoid(q @ k^T / 24) per batch, half
    {
        dim3 grid(16, 16, BATCH);
        mma_gemm<2><<<grid, 256, SMEM_SZ>>>(q, k, attn, NTOK, NTOK, CDIM,
            (long)NTOK * CDIM, (long)NTOK * CDIM, (long)NTOK * NTOK, NTOK, nullptr, nullptr);
    }

    // 5. O = attn @ Vt^T per batch (M=2048, N=576, K=2048)
    {
        dim3 grid(5, 16, BATCH);
        mma_gemm<1><<<grid, 256, SMEM_SZ>>>(attn, vt, o, NTOK, CDIM, NTOK,
            (long)NTOK * NTOK, (long)CDIM * NTOK, (long)NTOK * CDIM, CDIM, nullptr, nullptr);
    }

    // 6. P = O @ Wp^T + bp + xn_full  (fp32 out)
    {
        dim3 grid(5, 128, 1);
        mma_gemm<3><<<grid, 256, SMEM_SZ>>>(o, wp, p, ROWS, CDIM, CDIM, 0, 0, 0, CDIM, bp, xnf);
    }

    // 7. out = LN(P)
    ln_kernel<<<ROWS, 256>>>(p, gz, bz, out, nullptr);
}

// round 9
// speedup vs baseline: 1.4122x; 1.4122x over previous
#include <cuda_runtime.h>
#include <cuda_fp16.h>
#include <cstdint>

// ===========================================================================
// Cross_26998164423018  (B=8, N=2048, C=576, H=1)
// Round 8: R6 scalar-LDS fp16 m16n8k16 loop (ldmatrix reverted) + BK=64,
// 2-stage cp.async pipeline (half the syncs/waits), merged weight convert.
// ===========================================================================

#define CDIM   576
#define NTOK   2048
#define BATCH  8
#define ROWS   (BATCH * NTOK)          // 16384
#define ATT_SCALE 0.0416666679f        // 1/24

#define STAGES      2
#define ROW_BYTES   144                // 64 data halves (128B) + 8 pad
#define ROW_U32     36
#define TILE_BYTES  (128 * ROW_BYTES)               // 18432
#define STAGE_BYTES (2 * TILE_BYTES)                // A+B = 36864
#define EH          136                // half epilogue stride
#define EF          132                // float epilogue stride
#define SMEM_SZ     (STAGES * STAGE_BYTES)          // 73728 (2 CTA/SM)

// ------------------------- scratch (static device mem) ---------------------
__device__ float  g_xnf[(size_t)ROWS * CDIM];      // fp32 xn (residual)
__device__ __half g_xnh[(size_t)ROWS * CDIM];
__device__ __half g_ynh[(size_t)ROWS * CDIM];
__device__ __half g_wq [(size_t)CDIM * CDIM];
__device__ __half g_wk [(size_t)CDIM * CDIM];
__device__ __half g_wv [(size_t)CDIM * CDIM];
__device__ __half g_wp [(size_t)CDIM * CDIM];
__device__ __half g_q  [(size_t)ROWS * CDIM];
__device__ __half g_k  [(size_t)ROWS * CDIM];
__device__ __half g_vt [(size_t)BATCH * CDIM * NTOK];   // [b][n][t]
__device__ __half g_o  [(size_t)ROWS * CDIM];
__device__ __half g_attn[(size_t)BATCH * NTOK * NTOK];  // 67 MB
__device__ float  g_p  [(size_t)ROWS * CDIM];

// ------------------------------- helpers -----------------------------------
__device__ __forceinline__ uint32_t smem_u32(const void* p) {
    uint32_t a;
    asm("{ .reg .u64 t; cvta.to.shared.u64 t, %1; cvt.u32.u64 %0, t; }"
        : "=r"(a) : "l"(p));
    return a;
}
__device__ __forceinline__ void cpa16(uint32_t dst, const void* src, uint32_t sz) {
    asm volatile("cp.async.cg.shared.global [%0], [%1], 16, %2;"
                 :: "r"(dst), "l"(src), "r"(sz) : "memory");
}
__device__ __forceinline__ void cpa_commit() {
    asm volatile("cp.async.commit_group;" ::: "memory");
}
template<int Np> __device__ __forceinline__ void cpa_wait() {
    asm volatile("cp.async.wait_group %0;" :: "n"(Np) : "memory");
}
__device__ __forceinline__ void mma_f16(float* c, const uint32_t* a, const uint32_t* b) {
    asm volatile(
        "mma.sync.aligned.m16n8k16.row.col.f32.f16.f16.f32 "
        "{%0,%1,%2,%3}, {%4,%5,%6,%7}, {%8,%9}, {%0,%1,%2,%3};"
        : "+f"(c[0]), "+f"(c[1]), "+f"(c[2]), "+f"(c[3])
        : "r"(a[0]), "r"(a[1]), "r"(a[2]), "r"(a[3]), "r"(b[0]), "r"(b[1]));
}

// ===========================================================================
// fp16 mma.sync GEMM: C[M,N] = A[M,K] @ B[N,K]^T  (both K-major, half)
// grid: (x = N-tiles, y = M-tiles, z = batch), block = 256 (8 warps, 2x4)
// K must be a multiple of 64.
// EPI: 1 = half store, 2 = sigmoid(x/24) half store,
//      3 = fp32 store + bias[n] + resid[m,n], 4 = transposed half store (Vt)
// ===========================================================================
template<int EPI>
__global__ __launch_bounds__(256, 2) void mma_gemm(
    const __half* __restrict__ A, const __half* __restrict__ B,
    void* __restrict__ Cv, int M, int N, int K,
    long sAz, long sBz, long sCz, int ldC,
    const float* __restrict__ bias, const float* __restrict__ resid)
{
    extern __shared__ char smem[];
    const uint32_t sb = smem_u32(smem);
    const int tid  = threadIdx.x;
    const int lane = tid & 31;
    const int wid  = tid >> 5;
    const int m0 = blockIdx.y * 128;
    const int n0 = blockIdx.x * 128;
    const int z  = blockIdx.z;
    const int KT = K >> 6;

    // ---- gmem load mapping: thread owns row tid>>1, 64B half (tid&1) ----
    const int lrow  = tid >> 1;
    const int lhalf = tid & 1;
    const __half* aPtr = A + (size_t)z * sAz + (size_t)(m0 + lrow) * K + lhalf * 32;
    const int gn = n0 + lrow;
    const uint32_t bsz = (gn < N) ? 16u : 0u;
    const __half* bPtr = B + (size_t)z * sBz + (size_t)(gn < N ? gn : 0) * K + lhalf * 32;
    const uint32_t dA = sb + (uint32_t)lrow * ROW_BYTES + (uint32_t)lhalf * 64;
    const uint32_t dB = dA + TILE_BYTES;

    auto load_stage = [&](int s, int kt) {
        const uint32_t so = (uint32_t)s * STAGE_BYTES;
        const int k0 = kt * 64;
        #pragma unroll
        for (int j = 0; j < 4; j++) {
            cpa16(dA + so + j * 16, aPtr + k0 + j * 8, 16u);
            cpa16(dB + so + j * 16, bPtr + k0 + j * 8, bsz);
        }
    };

    // ---- accumulators & frag coords ----
    float acc[4][4][4];
    #pragma unroll
    for (int mt = 0; mt < 4; mt++)
        #pragma unroll
        for (int nt = 0; nt < 4; nt++)
            #pragma unroll
            for (int i = 0; i < 4; i++) acc[mt][nt][i] = 0.f;

    const int warp_m = wid & 1;
    const int warp_n = wid >> 1;
    const int gid = lane >> 2;           // groupID 0..7
    const int tig = lane & 3;            // thread-in-group
    const int arow = warp_m * 64 + gid;
    const int brow = warp_n * 32 + gid;

    // ---- pipeline prologue: both stages ----
    load_stage(0, 0); cpa_commit();
    load_stage(1, 1); cpa_commit();

    for (int kt = 0; kt < KT; kt++) {
        cpa_wait<1>();
        __syncthreads();                 // stage kt&1 ready, all warps aligned

        const uint32_t* uAs = (const uint32_t*)(smem + (kt & 1) * STAGE_BYTES);
        const uint32_t* uBs = uAs + 128 * ROW_U32;

        #pragma unroll
        for (int kk = 0; kk < 4; kk++) {
            const int kc = kk * 8 + tig;         // uint32 col index
            uint32_t af[4][4];
            #pragma unroll
            for (int mt = 0; mt < 4; mt++) {
                const int r = arow + mt * 16;
                af[mt][0] = uAs[r * ROW_U32 + kc];
                af[mt][1] = uAs[(r + 8) * ROW_U32 + kc];
                af[mt][2] = uAs[r * ROW_U32 + kc + 4];
                af[mt][3] = uAs[(r + 8) * ROW_U32 + kc + 4];
            }
            uint32_t bf[4][2];
            #pragma unroll
            for (int nt = 0; nt < 4; nt++) {
                const int n = brow + nt * 8;
                bf[nt][0] = uBs[n * ROW_U32 + kc];
                bf[nt][1] = uBs[n * ROW_U32 + kc + 4];
            }
            #pragma unroll
            for (int mt = 0; mt < 4; mt++)
                #pragma unroll
                for (int nt = 0; nt < 4; nt++)
                    mma_f16(acc[mt][nt], af[mt], bf[nt]);
        }

        __syncthreads();                 // all warps done reading stage kt&1
        if (kt + 2 < KT) load_stage(kt & 1, kt + 2);
        cpa_commit();                    // (possibly empty group keeps count)
    }

    // drain pending prefetches before reusing smem
    cpa_wait<0>();
    __syncthreads();

    // -------------------------------- epilogue --------------------------------
    if (EPI == 3) {
        float* eb = (float*)smem;   // [128][EF]
        #pragma unroll
        for (int mt = 0; mt < 4; mt++)
            #pragma unroll
            for (int i = 0; i < 4; i++) {
                const int r = warp_m * 64 + mt * 16 + gid + ((i >= 2) ? 8 : 0);
                #pragma unroll
                for (int nt = 0; nt < 4; nt++) {
                    const int c = warp_n * 32 + nt * 8 + tig * 2 + (i & 1);
                    eb[r * EF + c] = acc[mt][nt][i];
                }
            }
        __syncthreads();
        float* C = (float*)Cv;
        #pragma unroll
        for (int it = 0; it < 16; it++) {
            const int lin = it * 256 + tid;
            const int c4 = lin & 31, r = lin >> 5;
            const int n = n0 + c4 * 4;
            if (n < N) {
                float4 v4 = *(const float4*)(eb + r * EF + c4 * 4);
                const float4 bb = *(const float4*)(bias + n);
                const float4 rr = *(const float4*)(resid + (size_t)(m0 + r) * ldC + n);
                v4.x += bb.x + rr.x; v4.y += bb.y + rr.y;
                v4.z += bb.z + rr.z; v4.w += bb.w + rr.w;
                *(float4*)(C + (size_t)(m0 + r) * ldC + n) = v4;
            }
        }
        return;
    }

    __half* ebh = (__half*)smem;
    if (EPI == 4) {
        // transposed staging: ebh[n_local][t_local]
        #pragma unroll
        for (int mt = 0; mt < 4; mt++)
            #pragma unroll
            for (int i = 0; i < 4; i++) {
                const int r = warp_m * 64 + mt * 16 + gid + ((i >= 2) ? 8 : 0);
                #pragma unroll
                for (int nt = 0; nt < 4; nt++) {
                    const int c = warp_n * 32 + nt * 8 + tig * 2 + (i & 1);
                    ebh[c * EH + r] = __float2half_rn(acc[mt][nt][i]);
                }
            }
        __syncthreads();
        const int b = m0 >> 11, t0 = m0 & 2047;
        __half* vb = (__half*)Cv + (size_t)b * CDIM * NTOK + t0;
        #pragma unroll
        for (int it = 0; it < 8; it++) {
            const int lin = it * 256 + tid;
            const int t8 = (lin & 15) * 8, n = lin >> 4;
            if (n0 + n < N)
                *(uint4*)(vb + (size_t)(n0 + n) * NTOK + t8) =
                    *(const uint4*)(ebh + n * EH + t8);
        }
        return;
    }

    // EPI 1 / 2: half store, optionally sigmoid
    #pragma unroll
    for (int mt = 0; mt < 4; mt++)
        #pragma unroll
        for (int ih = 0; ih < 2; ih++) {       // c0c1 then c2c3 (row +8)
            const int r = warp_m * 64 + mt * 16 + gid + ih * 8;
            #pragma unroll
            for (int nt = 0; nt < 4; nt++) {
                const int c = warp_n * 32 + nt * 8 + tig * 2;
                float v0 = acc[mt][nt][ih * 2], v1 = acc[mt][nt][ih * 2 + 1];
                if (EPI == 2) {
                    v0 = 1.0f / (1.0f + __expf(-v0 * ATT_SCALE));
                    v1 = 1.0f / (1.0f + __expf(-v1 * ATT_SCALE));
                }
                *(__half2*)(ebh + r * EH + c) = __floats2half2_rn(v0, v1);
            }
        }
    __syncthreads();
    {
        __half* C = (__half*)Cv + (size_t)z * sCz;
        #pragma unroll
        for (int it = 0; it < 8; it++) {
            const int lin = it * 256 + tid;
            const int c8 = lin & 15, r = lin >> 4;
            const int n = n0 + c8 * 8;
            if (n < N)
                *(uint4*)(C + (size_t)(m0 + r) * ldC + n) =
                    *(const uint4*)(ebh + r * EH + c8 * 8);
        }
    }
}

// ===========================================================================
// LayerNorm over 576; writes fp32 and/or half output.
// ===========================================================================
__global__ __launch_bounds__(256) void ln_kernel(
    const float* __restrict__ x, const float* __restrict__ g,
    const float* __restrict__ b, float* __restrict__ out_f,
    __half* __restrict__ out_h)
{
    const long row = blockIdx.x;
    const float* xr = x + row * (long)CDIM;
    const int t = threadIdx.x;

    float v0 = xr[t];
    float v1 = xr[t + 256];
    float v2 = (t < 64) ? xr[t + 512] : 0.f;

    float s  = v0 + v1 + v2;
    float ss = v0 * v0 + v1 * v1 + v2 * v2;
    #pragma unroll
    for (int o = 16; o > 0; o >>= 1) {
        s  += __shfl_xor_sync(0xFFFFFFFFu, s,  o);
        ss += __shfl_xor_sync(0xFFFFFFFFu, ss, o);
    }
    __shared__ float sh_s[8], sh_ss[8];
    const int w = t >> 5, l = t & 31;
    if (l == 0) { sh_s[w] = s; sh_ss[w] = ss; }
    __syncthreads();
    float stot = 0.f, sstot = 0.f;
    #pragma unroll
    for (int i = 0; i < 8; i++) { stot += sh_s[i]; sstot += sh_ss[i]; }

    const float inv_n = 1.0f / (float)CDIM;
    const float mean = stot * inv_n;
    const float var  = sstot * inv_n - mean * mean;
    const float rstd = rsqrtf(var + 1e-5f);

    float o0 = (v0 - mean) * rstd * g[t]       + b[t];
    float o1 = (v1 - mean) * rstd * g[t + 256] + b[t + 256];
    float o2 = (t < 64) ? ((v2 - mean) * rstd * g[t + 512] + b[t + 512]) : 0.f;

    if (out_f) {
        out_f[row * (long)CDIM + t]       = o0;
        out_f[row * (long)CDIM + t + 256] = o1;
        if (t < 64) out_f[row * (long)CDIM + t + 512] = o2;
    }
    if (out_h) {
        out_h[row * (long)CDIM + t]       = __float2half_rn(o0);
        out_h[row * (long)CDIM + t + 256] = __float2half_rn(o1);
        if (t < 64) out_h[row * (long)CDIM + t + 512] = __float2half_rn(o2);
    }
}

// all 4 weight matrices in one launch; float4 -> 2x half2 per thread
__global__ void h_convert4(
    const float* __restrict__ s0, const float* __restrict__ s1,
    const float* __restrict__ s2, const float* __restrict__ s3,
    __half* __restrict__ d0, __half* __restrict__ d1,
    __half* __restrict__ d2, __half* __restrict__ d3, int n4)
{
    const int i = blockIdx.x * blockDim.x + threadIdx.x;
    if (i >= 4 * n4) return;
    const int sel = i / n4, j = i - sel * n4;
    const float* src = (sel == 0) ? s0 : (sel == 1) ? s1 : (sel == 2) ? s2 : s3;
    __half* dst      = (sel == 0) ? d0 : (sel == 1) ? d1 : (sel == 2) ? d2 : d3;
    const float4 v = *(const float4*)(src + j * 4);
    __half2 lo = __floats2half2_rn(v.x, v.y);
    __half2 hi = __floats2half2_rn(v.z, v.w);
    *(__half2*)(dst + j * 4)     = lo;
    *(__half2*)(dst + j * 4 + 2) = hi;
}

// ===========================================================================
extern "C" void kernel_launch(void* const* d_in, const int* in_sizes, int n_in,
                              void* d_out, int out_size)
{
    const float* x  = (const float*)d_in[0];
    const float* y  = (const float*)d_in[1];
    const float* Wq = (const float*)d_in[2];
    const float* Wk = (const float*)d_in[3];
    const float* Wv = (const float*)d_in[4];
    const float* Wp = (const float*)d_in[5];
    const float* bp = (const float*)d_in[6];
    const float* gx = (const float*)d_in[7];
    const float* bx = (const float*)d_in[8];
    const float* gy = (const float*)d_in[9];
    const float* by = (const float*)d_in[10];
    const float* gz = (const float*)d_in[11];
    const float* bz = (const float*)d_in[12];
    float* out = (float*)d_out;

    float *xnf, *p;
    __half *xnh, *ynh, *wq, *wk, *wv, *wp, *q, *k, *vt, *o, *attn;
    cudaGetSymbolAddress((void**)&xnf, g_xnf);
    cudaGetSymbolAddress((void**)&xnh, g_xnh);
    cudaGetSymbolAddress((void**)&ynh, g_ynh);
    cudaGetSymbolAddress((void**)&wq,  g_wq);
    cudaGetSymbolAddress((void**)&wk,  g_wk);
    cudaGetSymbolAddress((void**)&wv,  g_wv);
    cudaGetSymbolAddress((void**)&wp,  g_wp);
    cudaGetSymbolAddress((void**)&q,   g_q);
    cudaGetSymbolAddress((void**)&k,   g_k);
    cudaGetSymbolAddress((void**)&vt,  g_vt);
    cudaGetSymbolAddress((void**)&o,   g_o);
    cudaGetSymbolAddress((void**)&attn,g_attn);
    cudaGetSymbolAddress((void**)&p,   g_p);

    cudaFuncSetAttribute(mma_gemm<1>, cudaFuncAttributeMaxDynamicSharedMemorySize, SMEM_SZ);
    cudaFuncSetAttribute(mma_gemm<2>, cudaFuncAttributeMaxDynamicSharedMemorySize, SMEM_SZ);
    cudaFuncSetAttribute(mma_gemm<3>, cudaFuncAttributeMaxDynamicSharedMemorySize, SMEM_SZ);
    cudaFuncSetAttribute(mma_gemm<4>, cudaFuncAttributeMaxDynamicSharedMemorySize, SMEM_SZ);

    // 1. LayerNorms (fp32 residual copy + half operand copy)
    ln_kernel<<<ROWS, 256>>>(x, gx, bx, xnf, xnh);
    ln_kernel<<<ROWS, 256>>>(y, gy, by, nullptr, ynh);

    // 2. weights -> half (single launch)
    {
        const int n4 = CDIM * CDIM / 4;            // 82944
        const int nb = (4 * n4 + 255) / 256;
        h_convert4<<<nb, 256>>>(Wq, Wk, Wv, Wp, wq, wk, wv, wp, n4);
    }

    // 3. projections: q = yn@Wq^T, k = xn@Wk^T, Vt = (xn@Wv^T)^T per batch
    {
        dim3 grid(5, 128, 1);
        mma_gemm<1><<<grid, 256, SMEM_SZ>>>(ynh, wq, q,  ROWS, CDIM, CDIM, 0, 0, 0, CDIM, nullptr, nullptr);
        mma_gemm<1><<<grid, 256, SMEM_SZ>>>(xnh, wk, k,  ROWS, CDIM, CDIM, 0, 0, 0, CDIM, nullptr, nullptr);
        mma_gemm<4><<<grid, 256, SMEM_SZ>>>(xnh, wv, vt, ROWS, CDIM, CDIM, 0, 0, 0, CDIM, nullptr, nullptr);
    }

    // 4. attn = sigmoid(q @ k^T / 24) per batch, half
    {
        dim3 grid(16, 16, BATCH);
        mma_gemm<2><<<grid, 256, SMEM_SZ>>>(q, k, attn, NTOK, NTOK, CDIM,
            (long)NTOK * CDIM, (long)NTOK * CDIM, (long)NTOK * NTOK, NTOK, nullptr, nullptr);
    }

    // 5. O = attn @ Vt^T per batch (M=2048, N=576, K=2048)
    {
        dim3 grid(5, 16, BATCH);
        mma_gemm<1><<<grid, 256, SMEM_SZ>>>(attn, vt, o, NTOK, CDIM, NTOK,
            (long)NTOK * NTOK, (long)CDIM * NTOK, (long)NTOK * CDIM, CDIM, nullptr, nullptr);
    }

    // 6. P = O @ Wp^T + bp + xn_full  (fp32 out)
    {
        dim3 grid(5, 128, 1);
        mma_gemm<3><<<grid, 256, SMEM_SZ>>>(o, wp, p, ROWS, CDIM, CDIM, 0, 0, 0, CDIM, bp, xnf);
    }

    // 7. out = LN(P)
    ln_kernel<<<ROWS, 256>>>(p, gz, bz, out, nullptr);
}